// round 14
// baseline (speedup 1.0000x reference)
#include <cuda_runtime.h>
#include <cuda_fp16.h>
#include <math.h>
#include <stdint.h>

#define D_MODEL 4096
#define N_TOK   4096   // B*T
#define T_SEQ   2048
#define N_HEAD  32
#define H_DIM   128

// ---------------------------------------------------------------------------
// Scratch (allocation-free rule: __device__ globals)
// ---------------------------------------------------------------------------
__device__ __half g_xh [(size_t)N_TOK * D_MODEL];
__device__ __half g_wqh[(size_t)D_MODEL * D_MODEL];
__device__ __half g_wkh[(size_t)H_DIM * D_MODEL];
__device__ __half g_wvh[(size_t)H_DIM * D_MODEL];
__device__ __half g_woh[(size_t)D_MODEL * D_MODEL];
__device__ __half g_qh [(size_t)N_TOK * D_MODEL];
__device__ __half g_kh [(size_t)N_TOK * H_DIM];
__device__ __half g_vh [(size_t)N_TOK * H_DIM];
__device__ __half g_ah [(size_t)N_TOK * D_MODEL];
__device__ float  g_kvpart[(size_t)2 * 8 * N_TOK * H_DIM];   // [kv][split][row][col]

// ---------------------------------------------------------------------------
// PTX helpers (base sm_103 feature set: cp.async / ldmatrix / mma.sync)
// ---------------------------------------------------------------------------
__device__ __forceinline__ uint32_t smem_u32(const void* p) {
    uint32_t a;
    asm("{ .reg .u64 t; cvta.to.shared.u64 t, %1; cvt.u32.u64 %0, t; }"
        : "=r"(a) : "l"(p));
    return a;
}

#define CP_ASYNC16(saddr, gptr) \
    asm volatile("cp.async.cg.shared.global [%0], [%1], 16;" \
                 :: "r"(saddr), "l"(gptr))
#define CP_COMMIT()  asm volatile("cp.async.commit_group;" ::: "memory")
#define CP_WAIT(n)   asm volatile("cp.async.wait_group %0;" :: "n"(n) : "memory")

#define LDSM_X4(r0, r1, r2, r3, addr) \
    asm volatile("ldmatrix.sync.aligned.m8n8.x4.shared.b16 {%0,%1,%2,%3}, [%4];" \
                 : "=r"(r0), "=r"(r1), "=r"(r2), "=r"(r3) : "r"(addr))
#define LDSM_X4_T(r0, r1, r2, r3, addr) \
    asm volatile("ldmatrix.sync.aligned.m8n8.x4.trans.shared.b16 {%0,%1,%2,%3}, [%4];" \
                 : "=r"(r0), "=r"(r1), "=r"(r2), "=r"(r3) : "r"(addr))

#define MMA16816(d, a0, a1, a2, a3, b0, b1) \
    asm volatile("mma.sync.aligned.m16n8k16.row.col.f32.f16.f16.f32 " \
                 "{%0,%1,%2,%3}, {%4,%5,%6,%7}, {%8,%9}, {%0,%1,%2,%3};" \
                 : "+f"((d)[0]), "+f"((d)[1]), "+f"((d)[2]), "+f"((d)[3]) \
                 : "r"(a0), "r"(a1), "r"(a2), "r"(a3), "r"(b0), "r"(b1))

__device__ __forceinline__ uint32_t h2u(__half2 h) {
    return *reinterpret_cast<uint32_t*>(&h);
}

// ---------------------------------------------------------------------------
// Merged fp32 -> fp16 convert: one launch for x, wq, wk, wv, wo.
// ---------------------------------------------------------------------------
#define NX  ((size_t)N_TOK * D_MODEL)
#define NW  ((size_t)D_MODEL * D_MODEL)
#define NKV ((size_t)H_DIM * D_MODEL)
#define CVT_TOTAL (3 * NX + 2 * NKV)

__global__ void cvt_all_kernel(
    const float* __restrict__ x,  const float* __restrict__ wq,
    const float* __restrict__ wk, const float* __restrict__ wv,
    const float* __restrict__ wo,
    __half* __restrict__ xh, __half* __restrict__ wqh,
    __half* __restrict__ wkh, __half* __restrict__ wvh,
    __half* __restrict__ woh)
{
    size_t i = ((size_t)blockIdx.x * blockDim.x + threadIdx.x) * 4;
    const float* src; __half* dst; size_t off;
    if (i < NX)                     { src = x;  dst = xh;  off = i; }
    else if (i < NX + NW)           { src = wq; dst = wqh; off = i - NX; }
    else if (i < NX + NW + NKV)     { src = wk; dst = wkh; off = i - NX - NW; }
    else if (i < NX + NW + 2 * NKV) { src = wv; dst = wvh; off = i - NX - NW - NKV; }
    else                            { src = wo; dst = woh; off = i - NX - NW - 2 * NKV; }
    float4 f = *(const float4*)(src + off);
    __half2 h0 = __floats2half2_rn(f.x, f.y);
    __half2 h1 = __floats2half2_rn(f.z, f.w);
    *(uint2*)(dst + off) = make_uint2(h2u(h0), h2u(h1));
}

// ---------------------------------------------------------------------------
// GEMM core: BM=BN=128, BK=64, 128 threads / 4 warps, warp tile 64x64.
// 3-stage cp.async; ONE __syncthreads per k-tile; prefetch issued right
// after the barrier (before compute) so DRAM latency overlaps the MMAs.
// Buffer (kt+2)%3 was last read in iter kt-1; all warps passed this
// barrier -> WAR-safe.
// ---------------------------------------------------------------------------
#define GSTAGES 3
#define GEMM_SMEM (GSTAGES * 32768)

__device__ __forceinline__ void gemm_core(
    const __half* __restrict__ Ag0, const __half* __restrict__ Wg0,
    uint32_t sb, int NT, int kt0, int tid, float acc[4][8][4])
{
    const int sr = tid >> 3;
    const int sc = tid & 7;
    const int l = tid & 31, w = tid >> 5;
    const int wm = (w & 1) * 64, wn = (w >> 1) * 64;

    const __half* Ag = Ag0 + (size_t)sr * D_MODEL + sc * 8;
    const __half* Wg = Wg0 + (size_t)sr * D_MODEL + sc * 8;

    auto stage = [&](int kt) {
        const int st = kt % GSTAGES;
        const uint32_t ab = sb + st * 32768;
        const uint32_t bb = ab + 16384;
        const int k0 = (kt0 + kt) * 64;
#pragma unroll
        for (int it = 0; it < 8; it++) {
            const int r = sr + it * 16;
            const uint32_t soff = (uint32_t)(r * 128 + ((sc ^ (r & 7)) * 16));
            CP_ASYNC16(ab + soff, Ag + (size_t)(it * 16) * D_MODEL + k0);
            CP_ASYNC16(bb + soff, Wg + (size_t)(it * 16) * D_MODEL + k0);
        }
    };

    stage(0); CP_COMMIT();
    stage(1); CP_COMMIT();

#pragma unroll 1
    for (int kt = 0; kt < NT; kt++) {
        if (kt + 1 < NT) { CP_WAIT(1); }
        else { CP_WAIT(0); }
        __syncthreads();

        if (kt + 2 < NT) { stage(kt + 2); CP_COMMIT(); }

        const int st = kt % GSTAGES;
        const uint32_t ab = sb + st * 32768;
        const uint32_t bb = ab + 16384;

#pragma unroll
        for (int ks = 0; ks < 4; ks++) {
            uint32_t a[4][4], b[8][2];
#pragma unroll
            for (int i = 0; i < 4; i++) {
                const int row = wm + i * 16 + (l & 15);
                const int ch = ks * 2 + (l >> 4);
                LDSM_X4(a[i][0], a[i][1], a[i][2], a[i][3],
                        ab + row * 128 + ((ch ^ (row & 7)) * 16));
            }
#pragma unroll
            for (int jj = 0; jj < 4; jj++) {
                const int nrow = wn + jj * 16 + (l & 7) + ((l >> 4) & 1) * 8;
                const int ch = ks * 2 + ((l >> 3) & 1);
                LDSM_X4(b[jj * 2][0], b[jj * 2][1], b[jj * 2 + 1][0], b[jj * 2 + 1][1],
                        bb + nrow * 128 + ((ch ^ (nrow & 7)) * 16));
            }
#pragma unroll
            for (int i = 0; i < 4; i++)
#pragma unroll
                for (int j = 0; j < 8; j++)
                    MMA16816(acc[i][j], a[i][0], a[i][1], a[i][2], a[i][3],
                             b[j][0], b[j][1]);
        }
    }
}

// ---------------------------------------------------------------------------
// Fused QKV kernel (128 threads).
// ---------------------------------------------------------------------------
__global__ __launch_bounds__(128) void qkv_kernel(
    const __half* __restrict__ Xh,
    const __half* __restrict__ Wq, const __half* __restrict__ Wk,
    const __half* __restrict__ Wv,
    const float* __restrict__ qbias,
    __half* __restrict__ Qout, float* __restrict__ part)
{
    extern __shared__ char smc[];
    const uint32_t sb = smem_u32(smc);
    const int tid = threadIdx.x;
    const int l = tid & 31, w = tid >> 5;
    const int wm = (w & 1) * 64, wn = (w >> 1) * 64;

    const int bx = blockIdx.x;
    const bool isQ = bx < 1024;
    int m0, n0, kt0, NT, kv = 0, sp = 0;
    const __half* Wg_base;
    if (isQ) {
        m0 = (bx >> 5) * 128; n0 = (bx & 31) * 128; kt0 = 0; NT = 64;
        Wg_base = Wq;
    } else {
        const int t2 = bx - 1024;
        kv = t2 >> 8;
        const int rem = t2 & 255;
        m0 = (rem >> 3) * 128; n0 = 0; sp = rem & 7; kt0 = sp * 8; NT = 8;
        Wg_base = kv ? Wv : Wk;
    }

    float acc[4][8][4];
#pragma unroll
    for (int i = 0; i < 4; i++)
#pragma unroll
        for (int j = 0; j < 8; j++)
#pragma unroll
            for (int c = 0; c < 4; c++) acc[i][j][c] = 0.0f;

    gemm_core(Xh + (size_t)m0 * D_MODEL, Wg_base + (size_t)n0 * D_MODEL,
              sb, NT, kt0, tid, acc);

    if (isQ) {
#pragma unroll
        for (int i = 0; i < 4; i++) {
#pragma unroll
            for (int j = 0; j < 8; j++) {
                const int row = m0 + wm + i * 16 + (l >> 2);
                const int col = n0 + wn + j * 8 + (l & 3) * 2;
                const float b0 = qbias[col], b1 = qbias[col + 1];
                *reinterpret_cast<__half2*>(&Qout[(size_t)row * D_MODEL + col]) =
                    __floats2half2_rn(acc[i][j][0] + b0, acc[i][j][1] + b1);
                *reinterpret_cast<__half2*>(&Qout[(size_t)(row + 8) * D_MODEL + col]) =
                    __floats2half2_rn(acc[i][j][2] + b0, acc[i][j][3] + b1);
            }
        }
    } else {
        float* P = part + ((size_t)(kv * 8 + sp) * N_TOK + m0) * H_DIM;
#pragma unroll
        for (int i = 0; i < 4; i++) {
#pragma unroll
            for (int j = 0; j < 8; j++) {
                const int row = wm + i * 16 + (l >> 2);
                const int col = wn + j * 8 + (l & 3) * 2;
                *reinterpret_cast<float2*>(&P[(size_t)row * H_DIM + col]) =
                    make_float2(acc[i][j][0], acc[i][j][1]);
                *reinterpret_cast<float2*>(&P[(size_t)(row + 8) * H_DIM + col]) =
                    make_float2(acc[i][j][2], acc[i][j][3]);
            }
        }
    }
}

// ---------------------------------------------------------------------------
// O-projection GEMM (fp32 out), 128 threads, same core.
// ---------------------------------------------------------------------------
__global__ __launch_bounds__(128) void oproj_kernel(
    const __half* __restrict__ A, const __half* __restrict__ W,
    const float* __restrict__ bias, float* __restrict__ C)
{
    extern __shared__ char smc[];
    const uint32_t sb = smem_u32(smc);
    const int tid = threadIdx.x;
    const int l = tid & 31, w = tid >> 5;
    const int wm = (w & 1) * 64, wn = (w >> 1) * 64;
    const int m0 = blockIdx.y * 128, n0 = blockIdx.x * 128;

    float acc[4][8][4];
#pragma unroll
    for (int i = 0; i < 4; i++)
#pragma unroll
        for (int j = 0; j < 8; j++)
#pragma unroll
            for (int c = 0; c < 4; c++) acc[i][j][c] = 0.0f;

    gemm_core(A + (size_t)m0 * D_MODEL, W + (size_t)n0 * D_MODEL,
              sb, D_MODEL / 64, 0, tid, acc);

#pragma unroll
    for (int i = 0; i < 4; i++) {
#pragma unroll
        for (int j = 0; j < 8; j++) {
            const int row = m0 + wm + i * 16 + (l >> 2);
            const int col = n0 + wn + j * 8 + (l & 3) * 2;
            const float b0 = bias[col], b1 = bias[col + 1];
            *reinterpret_cast<float2*>(&C[(size_t)row * D_MODEL + col]) =
                make_float2(acc[i][j][0] + b0, acc[i][j][1] + b1);
            *reinterpret_cast<float2*>(&C[(size_t)(row + 8) * D_MODEL + col]) =
                make_float2(acc[i][j][2] + b0, acc[i][j][3] + b1);
        }
    }
}

// ---------------------------------------------------------------------------
// K/V split-K reduce: sum 8 partials + bias -> fp16
// ---------------------------------------------------------------------------
__global__ void kv_reduce_kernel(const float* __restrict__ part,
                                 const float* __restrict__ kbias,
                                 const float* __restrict__ vbias,
                                 __half* __restrict__ Kh, __half* __restrict__ Vh)
{
    const int i = (blockIdx.x * blockDim.x + threadIdx.x) * 4;
    const int half_n = N_TOK * H_DIM;
    const int kv = i >= half_n;
    const int j = i - kv * half_n;
    const int col = j & (H_DIM - 1);

    float4 s = make_float4(0.f, 0.f, 0.f, 0.f);
#pragma unroll
    for (int sp = 0; sp < 8; sp++) {
        float4 p = *(const float4*)&part[((size_t)(kv * 8 + sp) * N_TOK * H_DIM) + j];
        s.x += p.x; s.y += p.y; s.z += p.z; s.w += p.w;
    }
    const float* bias = kv ? vbias : kbias;
    float4 b = *(const float4*)&bias[col];
    __half* out = kv ? Vh : Kh;
    __half2 h0 = __floats2half2_rn(s.x + b.x, s.y + b.y);
    __half2 h1 = __floats2half2_rn(s.z + b.z, s.w + b.w);
    *(uint2*)(out + j) = make_uint2(h2u(h0), h2u(h1));
}

// ---------------------------------------------------------------------------
// Flash attention (causal), fp16 mma. CTA = 64 queries x head x batch,
// 128 threads / 4 warps, 2 CTAs/SM (smem 112KB). Q fragments preloaded to
// registers once (loop-invariant). KV triple-buffered; ONE sync/iter;
// prefetch issued before compute.
// ---------------------------------------------------------------------------
#define ATTN_SMEM (16384 + 3 * 32768)

__global__ __launch_bounds__(128) void attn_h_kernel(
    const __half* __restrict__ Qg, const __half* __restrict__ Kg,
    const __half* __restrict__ Vg, __half* __restrict__ Og)
{
    extern __shared__ char smc[];
    const uint32_t sb = smem_u32(smc);
    const int tid = threadIdx.x;
    const int l = tid & 31, w = tid >> 5;            // 4 warps
    const int qb = (T_SEQ / 64 - 1) - blockIdx.x;    // LPT: long CTAs first
    const int h = blockIdx.y, b = blockIdx.z;
    const size_t tok0 = (size_t)b * T_SEQ;
    const float fscale = 0.08838834764831845f;       // 1/sqrt(128)

    // stage Q (64 rows x 16 chunks, swizzled) + KV block 0 -> group 0
    {
#pragma unroll
        for (int it = 0; it < 8; it++) {
            const int idx = tid + it * 128;
            const int r = idx >> 4, ch = idx & 15;
            const __half* g = Qg + (tok0 + qb * 64 + r) * D_MODEL + h * H_DIM + ch * 8;
            CP_ASYNC16(sb + r * 256 + ((ch ^ (r & 7)) * 16), g);
        }
    }

    auto stage_kv = [&](int kb) {
        const uint32_t kbb = sb + 16384 + (kb % 3) * 32768;
        const uint32_t vbb = kbb + 16384;
#pragma unroll
        for (int it = 0; it < 8; it++) {
            const int idx = tid + it * 128;
            const int r = idx >> 4, ch = idx & 15;
            const uint32_t off = (uint32_t)(r * 256 + ((ch ^ (r & 7)) * 16));
            CP_ASYNC16(kbb + off, Kg + (tok0 + kb * 64 + r) * H_DIM + ch * 8);
            CP_ASYNC16(vbb + off, Vg + (tok0 + kb * 64 + r) * H_DIM + ch * 8);
        }
    };

    const int nb = qb + 1;

    stage_kv(0); CP_COMMIT();                       // group 0 = Q + KV0
    if (nb > 1) { stage_kv(1); CP_COMMIT(); }       // group 1 = KV1

    // wait for group 0 (Q + KV0), then preload Q fragments (loop-invariant)
    if (nb > 1) { CP_WAIT(1); } else { CP_WAIT(0); }
    __syncthreads();

    uint32_t aq[8][4];
    {
        const int row = w * 16 + (l & 15);
#pragma unroll
        for (int ks = 0; ks < 8; ks++) {
            const int ch = ks * 2 + (l >> 4);
            LDSM_X4(aq[ks][0], aq[ks][1], aq[ks][2], aq[ks][3],
                    sb + row * 256 + ((ch ^ (row & 7)) * 16));
        }
    }

    float o[16][4];
#pragma unroll
    for (int jt = 0; jt < 16; jt++)
#pragma unroll
        for (int c = 0; c < 4; c++) o[jt][c] = 0.0f;
    float mA = -1e30f, mB = -1e30f, lA = 0.0f, lB = 0.0f;

    const int rowA = qb * 64 + w * 16 + (l >> 2);

#pragma unroll 1
    for (int kb = 0; kb < nb; kb++) {
        if (kb > 0) {
            if (kb + 1 < nb) { CP_WAIT(1); }
            else { CP_WAIT(0); }
            __syncthreads();
        }
        // prefetch kb+2 before compute (buffer (kb+2)%3 last read in kb-1;
        // all warps passed the barrier above -> WAR-safe)
        if (kb + 2 < nb) { stage_kv(kb + 2); CP_COMMIT(); }

        const uint32_t kbb = sb + 16384 + (kb % 3) * 32768;
        const uint32_t vbb = kbb + 16384;

        float s[8][4];
#pragma unroll
        for (int j = 0; j < 8; j++)
#pragma unroll
            for (int c = 0; c < 4; c++) s[j][c] = 0.0f;

#pragma unroll
        for (int ks = 0; ks < 8; ks++) {
            uint32_t bf[8][2];
#pragma unroll
            for (int jj = 0; jj < 4; jj++) {
                const int nrow = jj * 16 + (l & 7) + ((l >> 4) & 1) * 8;
                const int ch = ks * 2 + ((l >> 3) & 1);
                LDSM_X4(bf[jj * 2][0], bf[jj * 2][1],
                        bf[jj * 2 + 1][0], bf[jj * 2 + 1][1],
                        kbb + nrow * 256 + ((ch ^ (nrow & 7)) * 16));
            }
#pragma unroll
            for (int j = 0; j < 8; j++)
                MMA16816(s[j], aq[ks][0], aq[ks][1], aq[ks][2], aq[ks][3],
                         bf[j][0], bf[j][1]);
        }

        if (kb == qb) {   // diagonal block
#pragma unroll
            for (int j = 0; j < 8; j++) {
                const int col = kb * 64 + j * 8 + (l & 3) * 2;
                if (col > rowA)     s[j][0] = -1e30f;
                if (col + 1 > rowA) s[j][1] = -1e30f;
                if (col > rowA + 8)     s[j][2] = -1e30f;
                if (col + 1 > rowA + 8) s[j][3] = -1e30f;
            }
        }

        float mlA = -1e30f, mlB = -1e30f;
#pragma unroll
        for (int j = 0; j < 8; j++) {
            mlA = fmaxf(mlA, fmaxf(s[j][0], s[j][1]));
            mlB = fmaxf(mlB, fmaxf(s[j][2], s[j][3]));
        }
        mlA = fmaxf(mlA, __shfl_xor_sync(0xffffffffu, mlA, 1));
        mlA = fmaxf(mlA, __shfl_xor_sync(0xffffffffu, mlA, 2));
        mlB = fmaxf(mlB, __shfl_xor_sync(0xffffffffu, mlB, 1));
        mlB = fmaxf(mlB, __shfl_xor_sync(0xffffffffu, mlB, 2));

        const float mnA = fmaxf(mA, mlA), mnB = fmaxf(mB, mlB);
        const float aA = __expf((mA - mnA) * fscale);
        const float aB = __expf((mB - mnB) * fscale);
        mA = mnA; mB = mnB;

        uint32_t pA[8], pB[8];
        float sumA = 0.0f, sumB = 0.0f;
#pragma unroll
        for (int j = 0; j < 8; j++) {
            const float e0 = __expf((s[j][0] - mA) * fscale);
            const float e1 = __expf((s[j][1] - mA) * fscale);
            const float e2 = __expf((s[j][2] - mB) * fscale);
            const float e3 = __expf((s[j][3] - mB) * fscale);
            sumA += e0 + e1; sumB += e2 + e3;
            pA[j] = h2u(__floats2half2_rn(e0, e1));
            pB[j] = h2u(__floats2half2_rn(e2, e3));
        }
        sumA += __shfl_xor_sync(0xffffffffu, sumA, 1);
        sumA += __shfl_xor_sync(0xffffffffu, sumA, 2);
        sumB += __shfl_xor_sync(0xffffffffu, sumB, 1);
        sumB += __shfl_xor_sync(0xffffffffu, sumB, 2);
        lA = lA * aA + sumA;
        lB = lB * aB + sumB;

#pragma unroll
        for (int jt = 0; jt < 16; jt++) {
            o[jt][0] *= aA; o[jt][1] *= aA;
            o[jt][2] *= aB; o[jt][3] *= aB;
        }

#pragma unroll
        for (int ks2 = 0; ks2 < 4; ks2++) {
            const uint32_t pa0 = pA[2 * ks2],     pa1 = pB[2 * ks2];
            const uint32_t pa2 = pA[2 * ks2 + 1], pa3 = pB[2 * ks2 + 1];
            const int key = ks2 * 16 + (l & 7) + ((l >> 3) & 1) * 8;
#pragma unroll
            for (int u = 0; u < 8; u++) {
                const int ch = 2 * u + (l >> 4);
                uint32_t v0, v1, v2, v3;
                LDSM_X4_T(v0, v1, v2, v3,
                          vbb + key * 256 + ((ch ^ (key & 7)) * 16));
                MMA16816(o[2 * u],     pa0, pa1, pa2, pa3, v0, v1);
                MMA16816(o[2 * u + 1], pa0, pa1, pa2, pa3, v2, v3);
            }
        }
    }

    const float invA = 1.0f / lA, invB = 1.0f / lB;
    const size_t rA = tok0 + qb * 64 + w * 16 + (l >> 2);
#pragma unroll
    for (int jt = 0; jt < 16; jt++) {
        const int col = h * H_DIM + jt * 8 + (l & 3) * 2;
        *reinterpret_cast<__half2*>(&Og[rA * D_MODEL + col]) =
            __floats2half2_rn(o[jt][0] * invA, o[jt][1] * invA);
        *reinterpret_cast<__half2*>(&Og[(rA + 8) * D_MODEL + col]) =
            __floats2half2_rn(o[jt][2] * invB, o[jt][3] * invB);
    }
}

// ---------------------------------------------------------------------------
extern "C" void kernel_launch(void* const* d_in, const int* in_sizes, int n_in,
                              void* d_out, int out_size)
{
    const float* x    = (const float*)d_in[0];
    const float* wq_w = (const float*)d_in[1];
    const float* wq_b = (const float*)d_in[2];
    const float* wk_w = (const float*)d_in[3];
    const float* wk_b = (const float*)d_in[4];
    const float* wv_w = (const float*)d_in[5];
    const float* wv_b = (const float*)d_in[6];
    const float* wo_w = (const float*)d_in[7];
    const float* wo_b = (const float*)d_in[8];
    float* out = (float*)d_out;

    __half *xh, *wqh, *wkh, *wvh, *woh, *qh, *kh, *vh, *ah;
    float* part;
    cudaGetSymbolAddress((void**)&xh,  g_xh);
    cudaGetSymbolAddress((void**)&wqh, g_wqh);
    cudaGetSymbolAddress((void**)&wkh, g_wkh);
    cudaGetSymbolAddress((void**)&wvh, g_wvh);
    cudaGetSymbolAddress((void**)&woh, g_woh);
    cudaGetSymbolAddress((void**)&qh,  g_qh);
    cudaGetSymbolAddress((void**)&kh,  g_kh);
    cudaGetSymbolAddress((void**)&vh,  g_vh);
    cudaGetSymbolAddress((void**)&ah,  g_ah);
    cudaGetSymbolAddress((void**)&part, g_kvpart);

    cudaFuncSetAttribute(qkv_kernel,
                         cudaFuncAttributeMaxDynamicSharedMemorySize, GEMM_SMEM);
    cudaFuncSetAttribute(oproj_kernel,
                         cudaFuncAttributeMaxDynamicSharedMemorySize, GEMM_SMEM);
    cudaFuncSetAttribute(attn_h_kernel,
                         cudaFuncAttributeMaxDynamicSharedMemorySize, ATTN_SMEM);

    // fp32 -> fp16 conversions (single merged launch)
    cvt_all_kernel<<<(int)(CVT_TOTAL / 1024), 256>>>(
        x, wq_w, wk_w, wv_w, wo_w, xh, wqh, wkh, wvh, woh);

    // Fused Q + split-K K/V projections
    qkv_kernel<<<1536, 128, GEMM_SMEM>>>(xh, wqh, wkh, wvh, wq_b, qh, part);
    kv_reduce_kernel<<<(2 * N_TOK * H_DIM) / 1024, 256>>>(part, wk_b, wv_b, kh, vh);

    // Causal flash attention (64-q CTAs, 2 CTAs/SM, LPT order)
    attn_h_kernel<<<dim3(T_SEQ / 64, N_HEAD, 2), 128, ATTN_SMEM>>>(qh, kh, vh, ah);

    // Output projection (fp32 out)
    oproj_kernel<<<dim3(D_MODEL / 128, N_TOK / 128), 128, GEMM_SMEM>>>(
        ah, woh, wo_b, out);
}

// round 15
// speedup vs baseline: 1.0286x; 1.0286x over previous
#include <cuda_runtime.h>
#include <cuda_fp16.h>
#include <math.h>
#include <stdint.h>

#define D_MODEL 4096
#define N_TOK   4096   // B*T
#define T_SEQ   2048
#define N_HEAD  32
#define H_DIM   128

// ---------------------------------------------------------------------------
// Scratch (allocation-free rule: __device__ globals)
// ---------------------------------------------------------------------------
__device__ __half g_xh [(size_t)N_TOK * D_MODEL];
__device__ __half g_wqh[(size_t)D_MODEL * D_MODEL];
__device__ __half g_wkh[(size_t)H_DIM * D_MODEL];
__device__ __half g_wvh[(size_t)H_DIM * D_MODEL];
__device__ __half g_woh[(size_t)D_MODEL * D_MODEL];
__device__ __half g_qh [(size_t)N_TOK * D_MODEL];
__device__ __half g_kh [(size_t)N_TOK * H_DIM];
__device__ __half g_vh [(size_t)N_TOK * H_DIM];
__device__ __half g_ah [(size_t)N_TOK * D_MODEL];
__device__ float  g_kvpart[(size_t)2 * 8 * N_TOK * H_DIM];   // [kv][split][row][col]

// ---------------------------------------------------------------------------
// PTX helpers (base sm_103 feature set: cp.async / ldmatrix / mma.sync)
// ---------------------------------------------------------------------------
__device__ __forceinline__ uint32_t smem_u32(const void* p) {
    uint32_t a;
    asm("{ .reg .u64 t; cvta.to.shared.u64 t, %1; cvt.u32.u64 %0, t; }"
        : "=r"(a) : "l"(p));
    return a;
}

#define CP_ASYNC16(saddr, gptr) \
    asm volatile("cp.async.cg.shared.global [%0], [%1], 16;" \
                 :: "r"(saddr), "l"(gptr))
#define CP_COMMIT()  asm volatile("cp.async.commit_group;" ::: "memory")
#define CP_WAIT(n)   asm volatile("cp.async.wait_group %0;" :: "n"(n) : "memory")

#define LDSM_X4(r0, r1, r2, r3, addr) \
    asm volatile("ldmatrix.sync.aligned.m8n8.x4.shared.b16 {%0,%1,%2,%3}, [%4];" \
                 : "=r"(r0), "=r"(r1), "=r"(r2), "=r"(r3) : "r"(addr))
#define LDSM_X4_T(r0, r1, r2, r3, addr) \
    asm volatile("ldmatrix.sync.aligned.m8n8.x4.trans.shared.b16 {%0,%1,%2,%3}, [%4];" \
                 : "=r"(r0), "=r"(r1), "=r"(r2), "=r"(r3) : "r"(addr))

#define MMA16816(d, a0, a1, a2, a3, b0, b1) \
    asm volatile("mma.sync.aligned.m16n8k16.row.col.f32.f16.f16.f32 " \
                 "{%0,%1,%2,%3}, {%4,%5,%6,%7}, {%8,%9}, {%0,%1,%2,%3};" \
                 : "+f"((d)[0]), "+f"((d)[1]), "+f"((d)[2]), "+f"((d)[3]) \
                 : "r"(a0), "r"(a1), "r"(a2), "r"(a3), "r"(b0), "r"(b1))

__device__ __forceinline__ uint32_t h2u(__half2 h) {
    return *reinterpret_cast<uint32_t*>(&h);
}

// ---------------------------------------------------------------------------
// Merged fp32 -> fp16 convert: one launch for x, wq, wk, wv, wo.
// ---------------------------------------------------------------------------
#define NX  ((size_t)N_TOK * D_MODEL)
#define NW  ((size_t)D_MODEL * D_MODEL)
#define NKV ((size_t)H_DIM * D_MODEL)
#define CVT_TOTAL (3 * NX + 2 * NKV)

__global__ void cvt_all_kernel(
    const float* __restrict__ x,  const float* __restrict__ wq,
    const float* __restrict__ wk, const float* __restrict__ wv,
    const float* __restrict__ wo,
    __half* __restrict__ xh, __half* __restrict__ wqh,
    __half* __restrict__ wkh, __half* __restrict__ wvh,
    __half* __restrict__ woh)
{
    size_t i = ((size_t)blockIdx.x * blockDim.x + threadIdx.x) * 4;
    const float* src; __half* dst; size_t off;
    if (i < NX)                     { src = x;  dst = xh;  off = i; }
    else if (i < NX + NW)           { src = wq; dst = wqh; off = i - NX; }
    else if (i < NX + NW + NKV)     { src = wk; dst = wkh; off = i - NX - NW; }
    else if (i < NX + NW + 2 * NKV) { src = wv; dst = wvh; off = i - NX - NW - NKV; }
    else                            { src = wo; dst = woh; off = i - NX - NW - 2 * NKV; }
    float4 f = *(const float4*)(src + off);
    __half2 h0 = __floats2half2_rn(f.x, f.y);
    __half2 h1 = __floats2half2_rn(f.z, f.w);
    *(uint2*)(dst + off) = make_uint2(h2u(h0), h2u(h1));
}

// ---------------------------------------------------------------------------
// GEMM core: BM=BN=128, BK=64, 128 threads / 4 warps, warp tile 64x64.
// 3-stage cp.async, ONE __syncthreads per k-tile (prefetch kt+2 after
// compute -- R13 placement, proven schedule).
// ---------------------------------------------------------------------------
#define GSTAGES 3
#define GEMM_SMEM (GSTAGES * 32768)

__device__ __forceinline__ void gemm_core(
    const __half* __restrict__ Ag0, const __half* __restrict__ Wg0,
    uint32_t sb, int NT, int kt0, int tid, float acc[4][8][4])
{
    const int sr = tid >> 3;
    const int sc = tid & 7;
    const int l = tid & 31, w = tid >> 5;
    const int wm = (w & 1) * 64, wn = (w >> 1) * 64;

    const __half* Ag = Ag0 + (size_t)sr * D_MODEL + sc * 8;
    const __half* Wg = Wg0 + (size_t)sr * D_MODEL + sc * 8;

    auto stage = [&](int kt) {
        const int st = kt % GSTAGES;
        const uint32_t ab = sb + st * 32768;
        const uint32_t bb = ab + 16384;
        const int k0 = (kt0 + kt) * 64;
#pragma unroll
        for (int it = 0; it < 8; it++) {
            const int r = sr + it * 16;
            const uint32_t soff = (uint32_t)(r * 128 + ((sc ^ (r & 7)) * 16));
            CP_ASYNC16(ab + soff, Ag + (size_t)(it * 16) * D_MODEL + k0);
            CP_ASYNC16(bb + soff, Wg + (size_t)(it * 16) * D_MODEL + k0);
        }
    };

    stage(0); CP_COMMIT();
    stage(1); CP_COMMIT();

#pragma unroll 1
    for (int kt = 0; kt < NT; kt++) {
        if (kt + 1 < NT) { CP_WAIT(1); }
        else { CP_WAIT(0); }
        __syncthreads();

        const int st = kt % GSTAGES;
        const uint32_t ab = sb + st * 32768;
        const uint32_t bb = ab + 16384;

#pragma unroll
        for (int ks = 0; ks < 4; ks++) {
            uint32_t a[4][4], b[8][2];
#pragma unroll
            for (int i = 0; i < 4; i++) {
                const int row = wm + i * 16 + (l & 15);
                const int ch = ks * 2 + (l >> 4);
                LDSM_X4(a[i][0], a[i][1], a[i][2], a[i][3],
                        ab + row * 128 + ((ch ^ (row & 7)) * 16));
            }
#pragma unroll
            for (int jj = 0; jj < 4; jj++) {
                const int nrow = wn + jj * 16 + (l & 7) + ((l >> 4) & 1) * 8;
                const int ch = ks * 2 + ((l >> 3) & 1);
                LDSM_X4(b[jj * 2][0], b[jj * 2][1], b[jj * 2 + 1][0], b[jj * 2 + 1][1],
                        bb + nrow * 128 + ((ch ^ (nrow & 7)) * 16));
            }
#pragma unroll
            for (int i = 0; i < 4; i++)
#pragma unroll
                for (int j = 0; j < 8; j++)
                    MMA16816(acc[i][j], a[i][0], a[i][1], a[i][2], a[i][3],
                             b[j][0], b[j][1]);
        }

        if (kt + 2 < NT) { stage(kt + 2); CP_COMMIT(); }
    }
}

// L2-locality swizzle: map a linear Q-tile index [0,1024) to (m,n) so that
// each consecutive group of 256 CTAs covers an 8m x 32n super-tile whose
// working set (8MB A + 32MB W) is L2-resident.
__device__ __forceinline__ void tile_swizzle(int t, int& m, int& n) {
    const int mg = t >> 8;          // super-tile row group (8 m-tiles)
    const int r  = t & 255;
    m = mg * 8 + (r & 7);
    n = r >> 3;
}

// ---------------------------------------------------------------------------
// Fused QKV kernel (128 threads).
//   bx < 1024: Q GEMM tile (L2-swizzled m,n), full K.
//   bx >= 1024: K/V split-K partial (8 k-iters), fp32 out.
// ---------------------------------------------------------------------------
__global__ __launch_bounds__(128) void qkv_kernel(
    const __half* __restrict__ Xh,
    const __half* __restrict__ Wq, const __half* __restrict__ Wk,
    const __half* __restrict__ Wv,
    const float* __restrict__ qbias,
    __half* __restrict__ Qout, float* __restrict__ part)
{
    extern __shared__ char smc[];
    const uint32_t sb = smem_u32(smc);
    const int tid = threadIdx.x;
    const int l = tid & 31, w = tid >> 5;
    const int wm = (w & 1) * 64, wn = (w >> 1) * 64;

    const int bx = blockIdx.x;
    const bool isQ = bx < 1024;
    int m0, n0, kt0, NT, kv = 0, sp = 0;
    const __half* Wg_base;
    if (isQ) {
        int mt, nt;
        tile_swizzle(bx, mt, nt);
        m0 = mt * 128; n0 = nt * 128; kt0 = 0; NT = 64;
        Wg_base = Wq;
    } else {
        const int t2 = bx - 1024;
        kv = t2 >> 8;
        const int rem = t2 & 255;
        m0 = (rem >> 3) * 128; n0 = 0; sp = rem & 7; kt0 = sp * 8; NT = 8;
        Wg_base = kv ? Wv : Wk;
    }

    float acc[4][8][4];
#pragma unroll
    for (int i = 0; i < 4; i++)
#pragma unroll
        for (int j = 0; j < 8; j++)
#pragma unroll
            for (int c = 0; c < 4; c++) acc[i][j][c] = 0.0f;

    gemm_core(Xh + (size_t)m0 * D_MODEL, Wg_base + (size_t)n0 * D_MODEL,
              sb, NT, kt0, tid, acc);

    if (isQ) {
#pragma unroll
        for (int i = 0; i < 4; i++) {
#pragma unroll
            for (int j = 0; j < 8; j++) {
                const int row = m0 + wm + i * 16 + (l >> 2);
                const int col = n0 + wn + j * 8 + (l & 3) * 2;
                const float b0 = qbias[col], b1 = qbias[col + 1];
                *reinterpret_cast<__half2*>(&Qout[(size_t)row * D_MODEL + col]) =
                    __floats2half2_rn(acc[i][j][0] + b0, acc[i][j][1] + b1);
                *reinterpret_cast<__half2*>(&Qout[(size_t)(row + 8) * D_MODEL + col]) =
                    __floats2half2_rn(acc[i][j][2] + b0, acc[i][j][3] + b1);
            }
        }
    } else {
        float* P = part + ((size_t)(kv * 8 + sp) * N_TOK + m0) * H_DIM;
#pragma unroll
        for (int i = 0; i < 4; i++) {
#pragma unroll
            for (int j = 0; j < 8; j++) {
                const int row = wm + i * 16 + (l >> 2);
                const int col = wn + j * 8 + (l & 3) * 2;
                *reinterpret_cast<float2*>(&P[(size_t)row * H_DIM + col]) =
                    make_float2(acc[i][j][0], acc[i][j][1]);
                *reinterpret_cast<float2*>(&P[(size_t)(row + 8) * H_DIM + col]) =
                    make_float2(acc[i][j][2], acc[i][j][3]);
            }
        }
    }
}

// ---------------------------------------------------------------------------
// O-projection GEMM (fp32 out), 128 threads, same core, L2-swizzled tiles.
// ---------------------------------------------------------------------------
__global__ __launch_bounds__(128) void oproj_kernel(
    const __half* __restrict__ A, const __half* __restrict__ W,
    const float* __restrict__ bias, float* __restrict__ C)
{
    extern __shared__ char smc[];
    const uint32_t sb = smem_u32(smc);
    const int tid = threadIdx.x;
    const int l = tid & 31, w = tid >> 5;
    const int wm = (w & 1) * 64, wn = (w >> 1) * 64;

    int mt, nt;
    tile_swizzle(blockIdx.x, mt, nt);
    const int m0 = mt * 128, n0 = nt * 128;

    float acc[4][8][4];
#pragma unroll
    for (int i = 0; i < 4; i++)
#pragma unroll
        for (int j = 0; j < 8; j++)
#pragma unroll
            for (int c = 0; c < 4; c++) acc[i][j][c] = 0.0f;

    gemm_core(A + (size_t)m0 * D_MODEL, W + (size_t)n0 * D_MODEL,
              sb, D_MODEL / 64, 0, tid, acc);

#pragma unroll
    for (int i = 0; i < 4; i++) {
#pragma unroll
        for (int j = 0; j < 8; j++) {
            const int row = m0 + wm + i * 16 + (l >> 2);
            const int col = n0 + wn + j * 8 + (l & 3) * 2;
            const float b0 = bias[col], b1 = bias[col + 1];
            *reinterpret_cast<float2*>(&C[(size_t)row * D_MODEL + col]) =
                make_float2(acc[i][j][0] + b0, acc[i][j][1] + b1);
            *reinterpret_cast<float2*>(&C[(size_t)(row + 8) * D_MODEL + col]) =
                make_float2(acc[i][j][2] + b0, acc[i][j][3] + b1);
        }
    }
}

// ---------------------------------------------------------------------------
// K/V split-K reduce: sum 8 partials + bias -> fp16
// ---------------------------------------------------------------------------
__global__ void kv_reduce_kernel(const float* __restrict__ part,
                                 const float* __restrict__ kbias,
                                 const float* __restrict__ vbias,
                                 __half* __restrict__ Kh, __half* __restrict__ Vh)
{
    const int i = (blockIdx.x * blockDim.x + threadIdx.x) * 4;
    const int half_n = N_TOK * H_DIM;
    const int kv = i >= half_n;
    const int j = i - kv * half_n;
    const int col = j & (H_DIM - 1);

    float4 s = make_float4(0.f, 0.f, 0.f, 0.f);
#pragma unroll
    for (int sp = 0; sp < 8; sp++) {
        float4 p = *(const float4*)&part[((size_t)(kv * 8 + sp) * N_TOK * H_DIM) + j];
        s.x += p.x; s.y += p.y; s.z += p.z; s.w += p.w;
    }
    const float* bias = kv ? vbias : kbias;
    float4 b = *(const float4*)&bias[col];
    __half* out = kv ? Vh : Kh;
    __half2 h0 = __floats2half2_rn(s.x + b.x, s.y + b.y);
    __half2 h1 = __floats2half2_rn(s.z + b.z, s.w + b.w);
    *(uint2*)(out + j) = make_uint2(h2u(h0), h2u(h1));
}

// ---------------------------------------------------------------------------
// Flash attention (causal), fp16 mma — exact R13 kernel (best measured).
// CTA = 64 queries x head x batch, 128 threads / 4 warps, 2 CTAs/SM.
// KV triple-buffered, ONE sync/iter, prefetch after compute.
// ---------------------------------------------------------------------------
#define ATTN_SMEM (16384 + 3 * 32768)

__global__ __launch_bounds__(128) void attn_h_kernel(
    const __half* __restrict__ Qg, const __half* __restrict__ Kg,
    const __half* __restrict__ Vg, __half* __restrict__ Og)
{
    extern __shared__ char smc[];
    const uint32_t sb = smem_u32(smc);
    const int tid = threadIdx.x;
    const int l = tid & 31, w = tid >> 5;            // 4 warps
    const int qb = (T_SEQ / 64 - 1) - blockIdx.x;    // LPT: long CTAs first
    const int h = blockIdx.y, b = blockIdx.z;
    const size_t tok0 = (size_t)b * T_SEQ;
    const float fscale = 0.08838834764831845f;       // 1/sqrt(128)

    {
#pragma unroll
        for (int it = 0; it < 8; it++) {
            const int idx = tid + it * 128;
            const int r = idx >> 4, ch = idx & 15;
            const __half* g = Qg + (tok0 + qb * 64 + r) * D_MODEL + h * H_DIM + ch * 8;
            CP_ASYNC16(sb + r * 256 + ((ch ^ (r & 7)) * 16), g);
        }
    }

    auto stage_kv = [&](int kb) {
        const uint32_t kbb = sb + 16384 + (kb % 3) * 32768;
        const uint32_t vbb = kbb + 16384;
#pragma unroll
        for (int it = 0; it < 8; it++) {
            const int idx = tid + it * 128;
            const int r = idx >> 4, ch = idx & 15;
            const uint32_t off = (uint32_t)(r * 256 + ((ch ^ (r & 7)) * 16));
            CP_ASYNC16(kbb + off, Kg + (tok0 + kb * 64 + r) * H_DIM + ch * 8);
            CP_ASYNC16(vbb + off, Vg + (tok0 + kb * 64 + r) * H_DIM + ch * 8);
        }
    };

    const int nb = qb + 1;

    stage_kv(0); CP_COMMIT();
    if (nb > 1) { stage_kv(1); CP_COMMIT(); }

    float o[16][4];
#pragma unroll
    for (int jt = 0; jt < 16; jt++)
#pragma unroll
        for (int c = 0; c < 4; c++) o[jt][c] = 0.0f;
    float mA = -1e30f, mB = -1e30f, lA = 0.0f, lB = 0.0f;

    const int rowA = qb * 64 + w * 16 + (l >> 2);

#pragma unroll 1
    for (int kb = 0; kb < nb; kb++) {
        if (kb + 1 < nb) { CP_WAIT(1); }
        else { CP_WAIT(0); }
        __syncthreads();

        const uint32_t kbb = sb + 16384 + (kb % 3) * 32768;
        const uint32_t vbb = kbb + 16384;

        float s[8][4];
#pragma unroll
        for (int j = 0; j < 8; j++)
#pragma unroll
            for (int c = 0; c < 4; c++) s[j][c] = 0.0f;

#pragma unroll
        for (int ks = 0; ks < 8; ks++) {
            uint32_t a0, a1, a2, a3;
            {
                const int row = w * 16 + (l & 15);
                const int ch = ks * 2 + (l >> 4);
                LDSM_X4(a0, a1, a2, a3, sb + row * 256 + ((ch ^ (row & 7)) * 16));
            }
            uint32_t bf[8][2];
#pragma unroll
            for (int jj = 0; jj < 4; jj++) {
                const int nrow = jj * 16 + (l & 7) + ((l >> 4) & 1) * 8;
                const int ch = ks * 2 + ((l >> 3) & 1);
                LDSM_X4(bf[jj * 2][0], bf[jj * 2][1],
                        bf[jj * 2 + 1][0], bf[jj * 2 + 1][1],
                        kbb + nrow * 256 + ((ch ^ (nrow & 7)) * 16));
            }
#pragma unroll
            for (int j = 0; j < 8; j++)
                MMA16816(s[j], a0, a1, a2, a3, bf[j][0], bf[j][1]);
        }

        if (kb == qb) {   // diagonal block
#pragma unroll
            for (int j = 0; j < 8; j++) {
                const int col = kb * 64 + j * 8 + (l & 3) * 2;
                if (col > rowA)     s[j][0] = -1e30f;
                if (col + 1 > rowA) s[j][1] = -1e30f;
                if (col > rowA + 8)     s[j][2] = -1e30f;
                if (col + 1 > rowA + 8) s[j][3] = -1e30f;
            }
        }

        float mlA = -1e30f, mlB = -1e30f;
#pragma unroll
        for (int j = 0; j < 8; j++) {
            mlA = fmaxf(mlA, fmaxf(s[j][0], s[j][1]));
            mlB = fmaxf(mlB, fmaxf(s[j][2], s[j][3]));
        }
        mlA = fmaxf(mlA, __shfl_xor_sync(0xffffffffu, mlA, 1));
        mlA = fmaxf(mlA, __shfl_xor_sync(0xffffffffu, mlA, 2));
        mlB = fmaxf(mlB, __shfl_xor_sync(0xffffffffu, mlB, 1));
        mlB = fmaxf(mlB, __shfl_xor_sync(0xffffffffu, mlB, 2));

        const float mnA = fmaxf(mA, mlA), mnB = fmaxf(mB, mlB);
        const float aA = __expf((mA - mnA) * fscale);
        const float aB = __expf((mB - mnB) * fscale);
        mA = mnA; mB = mnB;

        uint32_t pA[8], pB[8];
        float sumA = 0.0f, sumB = 0.0f;
#pragma unroll
        for (int j = 0; j < 8; j++) {
            const float e0 = __expf((s[j][0] - mA) * fscale);
            const float e1 = __expf((s[j][1] - mA) * fscale);
            const float e2 = __expf((s[j][2] - mB) * fscale);
            const float e3 = __expf((s[j][3] - mB) * fscale);
            sumA += e0 + e1; sumB += e2 + e3;
            pA[j] = h2u(__floats2half2_rn(e0, e1));
            pB[j] = h2u(__floats2half2_rn(e2, e3));
        }
        sumA += __shfl_xor_sync(0xffffffffu, sumA, 1);
        sumA += __shfl_xor_sync(0xffffffffu, sumA, 2);
        sumB += __shfl_xor_sync(0xffffffffu, sumB, 1);
        sumB += __shfl_xor_sync(0xffffffffu, sumB, 2);
        lA = lA * aA + sumA;
        lB = lB * aB + sumB;

#pragma unroll
        for (int jt = 0; jt < 16; jt++) {
            o[jt][0] *= aA; o[jt][1] *= aA;
            o[jt][2] *= aB; o[jt][3] *= aB;
        }

#pragma unroll
        for (int ks2 = 0; ks2 < 4; ks2++) {
            const uint32_t pa0 = pA[2 * ks2],     pa1 = pB[2 * ks2];
            const uint32_t pa2 = pA[2 * ks2 + 1], pa3 = pB[2 * ks2 + 1];
            const int key = ks2 * 16 + (l & 7) + ((l >> 3) & 1) * 8;
#pragma unroll
            for (int u = 0; u < 8; u++) {
                const int ch = 2 * u + (l >> 4);
                uint32_t v0, v1, v2, v3;
                LDSM_X4_T(v0, v1, v2, v3,
                          vbb + key * 256 + ((ch ^ (key & 7)) * 16));
                MMA16816(o[2 * u],     pa0, pa1, pa2, pa3, v0, v1);
                MMA16816(o[2 * u + 1], pa0, pa1, pa2, pa3, v2, v3);
            }
        }

        if (kb + 2 < nb) { stage_kv(kb + 2); CP_COMMIT(); }
    }

    const float invA = 1.0f / lA, invB = 1.0f / lB;
    const size_t rA = tok0 + qb * 64 + w * 16 + (l >> 2);
#pragma unroll
    for (int jt = 0; jt < 16; jt++) {
        const int col = h * H_DIM + jt * 8 + (l & 3) * 2;
        *reinterpret_cast<__half2*>(&Og[rA * D_MODEL + col]) =
            __floats2half2_rn(o[jt][0] * invA, o[jt][1] * invA);
        *reinterpret_cast<__half2*>(&Og[(rA + 8) * D_MODEL + col]) =
            __floats2half2_rn(o[jt][2] * invB, o[jt][3] * invB);
    }
}

// ---------------------------------------------------------------------------
extern "C" void kernel_launch(void* const* d_in, const int* in_sizes, int n_in,
                              void* d_out, int out_size)
{
    const float* x    = (const float*)d_in[0];
    const float* wq_w = (const float*)d_in[1];
    const float* wq_b = (const float*)d_in[2];
    const float* wk_w = (const float*)d_in[3];
    const float* wk_b = (const float*)d_in[4];
    const float* wv_w = (const float*)d_in[5];
    const float* wv_b = (const float*)d_in[6];
    const float* wo_w = (const float*)d_in[7];
    const float* wo_b = (const float*)d_in[8];
    float* out = (float*)d_out;

    __half *xh, *wqh, *wkh, *wvh, *woh, *qh, *kh, *vh, *ah;
    float* part;
    cudaGetSymbolAddress((void**)&xh,  g_xh);
    cudaGetSymbolAddress((void**)&wqh, g_wqh);
    cudaGetSymbolAddress((void**)&wkh, g_wkh);
    cudaGetSymbolAddress((void**)&wvh, g_wvh);
    cudaGetSymbolAddress((void**)&woh, g_woh);
    cudaGetSymbolAddress((void**)&qh,  g_qh);
    cudaGetSymbolAddress((void**)&kh,  g_kh);
    cudaGetSymbolAddress((void**)&vh,  g_vh);
    cudaGetSymbolAddress((void**)&ah,  g_ah);
    cudaGetSymbolAddress((void**)&part, g_kvpart);

    cudaFuncSetAttribute(qkv_kernel,
                         cudaFuncAttributeMaxDynamicSharedMemorySize, GEMM_SMEM);
    cudaFuncSetAttribute(oproj_kernel,
                         cudaFuncAttributeMaxDynamicSharedMemorySize, GEMM_SMEM);
    cudaFuncSetAttribute(attn_h_kernel,
                         cudaFuncAttributeMaxDynamicSharedMemorySize, ATTN_SMEM);

    // fp32 -> fp16 conversions (single merged launch)
    cvt_all_kernel<<<(int)(CVT_TOTAL / 1024), 256>>>(
        x, wq_w, wk_w, wv_w, wo_w, xh, wqh, wkh, wvh, woh);

    // Fused Q + split-K K/V projections (Q tiles L2-swizzled)
    qkv_kernel<<<1536, 128, GEMM_SMEM>>>(xh, wqh, wkh, wvh, wq_b, qh, part);
    kv_reduce_kernel<<<(2 * N_TOK * H_DIM) / 1024, 256>>>(part, wk_b, wv_b, kh, vh);

    // Causal flash attention (exact R13 kernel)
    attn_h_kernel<<<dim3(T_SEQ / 64, N_HEAD, 2), 128, ATTN_SMEM>>>(qh, kh, vh, ah);

    // Output projection (fp32 out, L2-swizzled tiles)
    oproj_kernel<<<1024, 128, GEMM_SMEM>>>(ah, woh, wo_b, out);
}